// round 2
// baseline (speedup 1.0000x reference)
#include <cuda_runtime.h>

#define MAXN 50000
#define MAXE 1600000

// ---------------- scratch (static device allocations) ----------------
__device__ int   g_is64;
__device__ int   g_cnt[MAXN];
__device__ int   g_rowptr[MAXN + 1];
__device__ int   g_cursor[MAXN];
__device__ int   g_part[128];
__device__ int   g_adj[MAXE + MAXN];
__device__ float g_h1pre[MAXN * 64];
__device__ float g_h1post[MAXN * 64];
__device__ float g_h2pre[MAXN * 32];
__device__ float g_h2post[MAXN * 32];
__device__ float g_al1s[MAXN * 8], g_al1d[MAXN * 8];
__device__ float g_al2s[MAXN * 8], g_al2d[MAXN * 8];
__device__ float g_Mf[16 * 32];
__device__ float g_cf[16];

// read edge value i (src row: i in [0,E); dst row: i in [E,2E))
__device__ __forceinline__ int edge_val(const void* ei, long long idx) {
    return g_is64 ? (int)((const long long*)ei)[idx] : ((const int*)ei)[idx];
}

// ---------------- dtype probe + CSR build ----------------
__global__ void k_zero(int N) {
    int i = blockIdx.x * blockDim.x + threadIdx.x;
    if (i < N) g_cnt[i] = 0;
    if (i == 0) g_is64 = 1;  // optimistic; k_detect may clear
}

__global__ void k_detect(const unsigned long long* __restrict__ w, int E) {
    // Safe to read min(E,2048) 8-byte words under either dtype
    // (int64 buffer has 2E words, int32 buffer has E words).
    int n = E < 2048 ? E : 2048;
    int i = blockIdx.x * blockDim.x + threadIdx.x;
    if (i < n && (w[i] >> 32) != 0ull) g_is64 = 0;  // high half set => int32 pairs
}

__global__ void k_count(const void* __restrict__ ei, int E) {
    int i = blockIdx.x * blockDim.x + threadIdx.x;
    if (i < E) {
        int d = edge_val(ei, (long long)E + i);
        atomicAdd(&g_cnt[d], 1);
    }
}

__global__ void k_blocksum(int N) {
    __shared__ int sh[1024];
    int i = blockIdx.x * 1024 + threadIdx.x;
    sh[threadIdx.x] = (i < N) ? (g_cnt[i] + 1) : 0;  // +1 = self loop
    __syncthreads();
    for (int o = 512; o > 0; o >>= 1) {
        if (threadIdx.x < o) sh[threadIdx.x] += sh[threadIdx.x + o];
        __syncthreads();
    }
    if (threadIdx.x == 0) g_part[blockIdx.x] = sh[0];
}

__global__ void k_scanpart(int nb) {
    if (threadIdx.x == 0) {
        int acc = 0;
        for (int b = 0; b < nb; b++) { int t = g_part[b]; g_part[b] = acc; acc += t; }
    }
}

__global__ void k_scan(int N) {
    __shared__ int sh[1024];
    int i = blockIdx.x * 1024 + threadIdx.x;
    int v = (i < N) ? (g_cnt[i] + 1) : 0;
    sh[threadIdx.x] = v;
    __syncthreads();
    for (int o = 1; o < 1024; o <<= 1) {
        int t = 0;
        if (threadIdx.x >= (unsigned)o) t = sh[threadIdx.x - o];
        __syncthreads();
        sh[threadIdx.x] += t;
        __syncthreads();
    }
    if (i < N) {
        int incl = sh[threadIdx.x] + g_part[blockIdx.x];
        g_rowptr[i + 1] = incl;
        g_cursor[i] = incl - v;
        if (i == 0) g_rowptr[0] = 0;
    }
}

__global__ void k_scatter(const void* __restrict__ ei, int E) {
    int i = blockIdx.x * blockDim.x + threadIdx.x;
    if (i >= E) return;
    int d = edge_val(ei, (long long)E + i);
    int s = edge_val(ei, i);
    int pos = atomicAdd(&g_cursor[d], 1);
    g_adj[pos] = s;
}

__global__ void k_self(int N) {
    int i = blockIdx.x * blockDim.x + threadIdx.x;
    if (i < N) {
        int pos = atomicAdd(&g_cursor[i], 1);
        g_adj[pos] = i;
    }
}

// ---------------- dense GEMM  Y[N,FOUT] = X[N,FIN] @ W[FIN,FOUT] ----------------
template <int FIN, int FOUT, int NPB, int LAYER>
__global__ __launch_bounds__(FOUT * NPB) void k_gemm(const float* __restrict__ Xext,
                                                     const float* __restrict__ W, int N) {
    const float* __restrict__ X = (LAYER == 1) ? Xext : g_h1post;
    float* __restrict__ Y = (LAYER == 1) ? g_h1pre : g_h2pre;
    __shared__ float Ws[FIN * FOUT];
    __shared__ float Xs[NPB][FIN];
    int tid = threadIdx.x;
    int tx = tid % FOUT, ty = tid / FOUT;
    for (int idx = tid; idx < FIN * FOUT; idx += FOUT * NPB) Ws[idx] = W[idx];
    int n = blockIdx.x * NPB + ty;
    for (int k = tx; k < FIN; k += FOUT) Xs[ty][k] = (n < N) ? X[n * FIN + k] : 0.f;
    __syncthreads();
    float sum = 0.f;
#pragma unroll
    for (int k = 0; k < FIN; k++) sum = fmaf(Xs[ty][k], Ws[k * FOUT + tx], sum);
    if (n < N) Y[n * FOUT + tx] = sum;
}

// ---------------- per-node attention logits ----------------
template <int C, int LAYER>
__global__ void k_al(const float* __restrict__ a_src, const float* __restrict__ a_dst, int N) {
    constexpr int F = 8 * C;
    const float* __restrict__ H = (LAYER == 1) ? g_h1pre : g_h2pre;
    float* __restrict__ als = (LAYER == 1) ? g_al1s : g_al2s;
    float* __restrict__ ald = (LAYER == 1) ? g_al1d : g_al2d;
    int n = blockIdx.x * blockDim.x + threadIdx.x;
    if (n >= N) return;
    float hr[F];
#pragma unroll
    for (int q = 0; q < F / 4; q++) {
        float4 v = *reinterpret_cast<const float4*>(&H[n * F + q * 4]);
        hr[q * 4 + 0] = v.x; hr[q * 4 + 1] = v.y; hr[q * 4 + 2] = v.z; hr[q * 4 + 3] = v.w;
    }
#pragma unroll
    for (int t = 0; t < 8; t++) {
        float ss = 0.f, dd = 0.f;
#pragma unroll
        for (int c = 0; c < C; c++) {
            float hv = hr[t * C + c];
            ss = fmaf(hv, __ldg(&a_src[t * C + c]), ss);
            dd = fmaf(hv, __ldg(&a_dst[t * C + c]), dd);
        }
        als[n * 8 + t] = ss;
        ald[n * 8 + t] = dd;
    }
}

// ---------------- GAT aggregation: warp-group per dst node ----------------
template <int C, int LAYER>
__global__ __launch_bounds__(256) void k_agg(const float* __restrict__ bias, int N) {
    constexpr int F = 8 * C;     // 64 / 32
    constexpr int G = F / 2;     // lanes per node: 32 / 16
    constexpr int NPW = 32 / G;  // nodes per warp
    const float* __restrict__ H = (LAYER == 1) ? g_h1pre : g_h2pre;
    const float* __restrict__ als = (LAYER == 1) ? g_al1s : g_al2s;
    const float* __restrict__ ald = (LAYER == 1) ? g_al1d : g_al2d;
    float* __restrict__ outp = (LAYER == 1) ? g_h1post : g_h2post;

    int warp = (blockIdx.x * blockDim.x + threadIdx.x) >> 5;
    int lane = threadIdx.x & 31;
    int group = lane / G, gl = lane % G;
    int node = warp * NPW + group;
    bool valid = node < N;
    int base = 0, deg = 0;
    if (valid) { base = g_rowptr[node]; deg = g_rowptr[node + 1] - base; }

    float ad[8];
#pragma unroll
    for (int t = 0; t < 8; t++) ad[t] = valid ? ald[node * 8 + t] : 0.f;

    // ---- pass 1a: per-head max over incoming edges ----
    float m[8];
#pragma unroll
    for (int t = 0; t < 8; t++) m[t] = -1e30f;
    for (int e = gl; e < deg; e += G) {
        int sid = __ldg(&g_adj[base + e]);
#pragma unroll
        for (int t = 0; t < 8; t++) {
            float a = __ldg(&als[sid * 8 + t]) + ad[t];
            a = a > 0.f ? a : 0.2f * a;
            m[t] = fmaxf(m[t], a);
        }
    }
#pragma unroll
    for (int off = G / 2; off > 0; off >>= 1)
#pragma unroll
        for (int t = 0; t < 8; t++)
            m[t] = fmaxf(m[t], __shfl_xor_sync(0xffffffffu, m[t], off));

    // ---- pass 1b: per-head exp-sum ----
    float s[8];
#pragma unroll
    for (int t = 0; t < 8; t++) s[t] = 0.f;
    for (int e = gl; e < deg; e += G) {
        int sid = __ldg(&g_adj[base + e]);
#pragma unroll
        for (int t = 0; t < 8; t++) {
            float a = __ldg(&als[sid * 8 + t]) + ad[t];
            a = a > 0.f ? a : 0.2f * a;
            s[t] += __expf(a - m[t]);
        }
    }
#pragma unroll
    for (int off = G / 2; off > 0; off >>= 1)
#pragma unroll
        for (int t = 0; t < 8; t++)
            s[t] += __shfl_xor_sync(0xffffffffu, s[t], off);

    // ---- pass 2: coalesced weighted feature accumulation ----
    int hh = (2 * gl) / C;
    float mh = m[hh];
    float ish = 1.f / (s[hh] + 1e-16f);
    float adh = ad[hh];
    float a0 = 0.f, a1 = 0.f;
#pragma unroll 2
    for (int j = 0; j < deg; j++) {
        int sid = __ldg(&g_adj[base + j]);
        float a = __ldg(&als[sid * 8 + hh]) + adh;
        a = a > 0.f ? a : 0.2f * a;
        float alpha = __expf(a - mh) * ish;
        float2 f = *reinterpret_cast<const float2*>(&H[sid * F + 2 * gl]);
        a0 = fmaf(f.x, alpha, a0);
        a1 = fmaf(f.y, alpha, a1);
    }
    if (valid) {
        float o0 = a0 + __ldg(&bias[2 * gl]);
        float o1 = a1 + __ldg(&bias[2 * gl + 1]);
        o0 = o0 > 0.f ? o0 : (expf(o0) - 1.f);  // elu
        o1 = o1 > 0.f ? o1 : (expf(o1) - 1.f);
        *reinterpret_cast<float2*>(&outp[node * F + 2 * gl]) = make_float2(o0, o1);
    }
}

// ---------------- fold MHA(v-path)+out_proj+fc into one 16x32 matrix ----------------
__global__ void k_prep(const float* __restrict__ in_w, const float* __restrict__ in_b,
                       const float* __restrict__ ow, const float* __restrict__ ob,
                       const float* __restrict__ fw, const float* __restrict__ fb) {
    __shared__ float T[32 * 32];
    __shared__ float u[32];
    int tid = threadIdx.x;  // 1024
    {
        int r = tid >> 5, j = tid & 31;
        float acc = 0.f;
        for (int p = 0; p < 32; p++) acc = fmaf(ow[r * 32 + p], in_w[(64 + p) * 32 + j], acc);
        T[r * 32 + j] = acc;
    }
    if (tid < 32) {
        float acc = ob[tid];
        for (int p = 0; p < 32; p++) acc = fmaf(ow[tid * 32 + p], in_b[64 + p], acc);
        u[tid] = acc;
    }
    __syncthreads();
    if (tid < 512) {
        int i = tid >> 5, j = tid & 31;
        float acc = 0.f;
        for (int r = 0; r < 32; r++) acc = fmaf(fw[i * 32 + r], T[r * 32 + j], acc);
        g_Mf[i * 32 + j] = acc;
    }
    if (tid < 16) {
        float acc = fb[tid];
        for (int r = 0; r < 32; r++) acc = fmaf(fw[tid * 32 + r], u[r], acc);
        g_cf[tid] = acc;
    }
}

// ---------------- logits + log_softmax ----------------
__global__ void k_logits(float* __restrict__ out, int N) {
    int n = blockIdx.x * blockDim.x + threadIdx.x;
    if (n >= N) return;
    float hr[32];
#pragma unroll
    for (int q = 0; q < 8; q++) {
        float4 v = *reinterpret_cast<const float4*>(&g_h2post[n * 32 + q * 4]);
        hr[q * 4 + 0] = v.x; hr[q * 4 + 1] = v.y; hr[q * 4 + 2] = v.z; hr[q * 4 + 3] = v.w;
    }
    float l[16];
#pragma unroll
    for (int i = 0; i < 16; i++) {
        float acc = g_cf[i];
#pragma unroll
        for (int j = 0; j < 32; j++) acc = fmaf(g_Mf[i * 32 + j], hr[j], acc);
        l[i] = acc;
    }
    float mx = l[0];
#pragma unroll
    for (int i = 1; i < 16; i++) mx = fmaxf(mx, l[i]);
    float se = 0.f;
#pragma unroll
    for (int i = 0; i < 16; i++) se += expf(l[i] - mx);
    float lse = mx + logf(se);
#pragma unroll
    for (int q = 0; q < 4; q++) {
        float4 v = make_float4(l[q * 4 + 0] - lse, l[q * 4 + 1] - lse,
                               l[q * 4 + 2] - lse, l[q * 4 + 3] - lse);
        *reinterpret_cast<float4*>(&out[n * 16 + q * 4]) = v;
    }
}

// ---------------- launcher ----------------
extern "C" void kernel_launch(void* const* d_in, const int* in_sizes, int n_in,
                              void* d_out, int out_size) {
    const float* x = (const float*)d_in[0];
    const void* ei = d_in[1];
    const float* W1 = (const float*)d_in[2];
    const float* a1s = (const float*)d_in[3];
    const float* a1d = (const float*)d_in[4];
    const float* b1 = (const float*)d_in[5];
    const float* W2 = (const float*)d_in[6];
    const float* a2s = (const float*)d_in[7];
    const float* a2d = (const float*)d_in[8];
    const float* b2 = (const float*)d_in[9];
    const float* ipw = (const float*)d_in[10];
    const float* ipb = (const float*)d_in[11];
    const float* opw = (const float*)d_in[12];
    const float* opb = (const float*)d_in[13];
    const float* fw = (const float*)d_in[14];
    const float* fb = (const float*)d_in[15];

    int N = in_sizes[0] / 128;
    int E = in_sizes[1] / 2;

    // CSR by dst (reused by both GAT layers)
    k_zero<<<(N + 255) / 256, 256>>>(N);
    k_detect<<<(2048 + 255) / 256, 256>>>((const unsigned long long*)ei, E);
    k_count<<<(E + 255) / 256, 256>>>(ei, E);
    int nb = (N + 1023) / 1024;
    k_blocksum<<<nb, 1024>>>(N);
    k_scanpart<<<1, 32>>>(nb);
    k_scan<<<nb, 1024>>>(N);
    k_scatter<<<(E + 255) / 256, 256>>>(ei, E);
    k_self<<<(N + 255) / 256, 256>>>(N);

    // GAT layer 1: 128 -> 8 heads x 8
    k_gemm<128, 64, 4, 1><<<(N + 3) / 4, 256>>>(x, W1, N);
    k_al<8, 1><<<(N + 127) / 128, 128>>>(a1s, a1d, N);
    k_agg<8, 1><<<(N + 7) / 8, 256>>>(b1, N);

    // GAT layer 2: 64 -> 8 heads x 4
    k_gemm<64, 32, 8, 2><<<(N + 7) / 8, 256>>>(x, W2, N);
    k_al<4, 2><<<(N + 127) / 128, 128>>>(a2s, a2d, N);
    k_agg<4, 2><<<(N + 15) / 16, 256>>>(b2, N);

    // collapsed MHA + fc + log_softmax
    k_prep<<<1, 1024>>>(ipw, ipb, opw, opb, fw, fb);
    k_logits<<<(N + 127) / 128, 128>>>((float*)d_out, N);
}

// round 3
// speedup vs baseline: 1.6630x; 1.6630x over previous
#include <cuda_runtime.h>

#define MAXN 50000
#define MAXE 1600000

// ---------------- scratch (static device allocations) ----------------
__device__ int   g_is64;
__device__ int   g_cnt[MAXN];
__device__ int   g_rowptr[MAXN + 1];
__device__ int   g_cursor[MAXN];
__device__ int   g_part[128];
__device__ int   g_adj[MAXE + MAXN];
__device__ __align__(16) float g_h1pre[MAXN * 64];
__device__ __align__(16) float g_h1post[MAXN * 64];
__device__ __align__(16) float g_h2pre[MAXN * 32];
__device__ __align__(16) float g_h2post[MAXN * 32];
__device__ float g_al1s[MAXN * 8], g_al1d[MAXN * 8];
__device__ float g_al2s[MAXN * 8], g_al2d[MAXN * 8];
__device__ float g_Mf[16 * 32];
__device__ float g_cf[16];

// read edge value i (src row: i in [0,E); dst row: i in [E,2E))
__device__ __forceinline__ int edge_val(const void* ei, long long idx) {
    return g_is64 ? (int)((const long long*)ei)[idx] : ((const int*)ei)[idx];
}

// ---------------- dtype probe + CSR build ----------------
__global__ void k_zero(const unsigned long long* __restrict__ w, int N, int E) {
    int i = blockIdx.x * blockDim.x + threadIdx.x;
    if (i < N) g_cnt[i] = 0;
    if (i == 0) g_is64 = 1;  // optimistic; cleared below if int32
    // dtype probe: safe to read min(E,2048) 8-byte words under either dtype
    int n = E < 2048 ? E : 2048;
    if (i < n && (w[i] >> 32) != 0ull) g_is64 = 0;  // high half set => int32 pairs
}

__global__ void k_count(const void* __restrict__ ei, int E) {
    int i = blockIdx.x * blockDim.x + threadIdx.x;
    if (i < E) {
        int d = edge_val(ei, (long long)E + i);
        atomicAdd(&g_cnt[d], 1);
    }
}

__global__ void k_blocksum(int N) {
    __shared__ int sh[1024];
    int i = blockIdx.x * 1024 + threadIdx.x;
    sh[threadIdx.x] = (i < N) ? (g_cnt[i] + 1) : 0;  // +1 = self loop
    __syncthreads();
    for (int o = 512; o > 0; o >>= 1) {
        if (threadIdx.x < o) sh[threadIdx.x] += sh[threadIdx.x + o];
        __syncthreads();
    }
    if (threadIdx.x == 0) g_part[blockIdx.x] = sh[0];
}

__global__ void k_scanpart(int nb) {
    if (threadIdx.x == 0) {
        int acc = 0;
        for (int b = 0; b < nb; b++) { int t = g_part[b]; g_part[b] = acc; acc += t; }
    }
}

__global__ void k_scan(int N) {
    __shared__ int sh[1024];
    int i = blockIdx.x * 1024 + threadIdx.x;
    int v = (i < N) ? (g_cnt[i] + 1) : 0;
    sh[threadIdx.x] = v;
    __syncthreads();
    for (int o = 1; o < 1024; o <<= 1) {
        int t = 0;
        if (threadIdx.x >= (unsigned)o) t = sh[threadIdx.x - o];
        __syncthreads();
        sh[threadIdx.x] += t;
        __syncthreads();
    }
    if (i < N) {
        int incl = sh[threadIdx.x] + g_part[blockIdx.x];
        g_rowptr[i + 1] = incl;
        g_cursor[i] = incl - v;
        if (i == 0) g_rowptr[0] = 0;
    }
}

__global__ void k_scatter(const void* __restrict__ ei, int E, int N) {
    int i = blockIdx.x * blockDim.x + threadIdx.x;
    if (i < E) {
        int d = edge_val(ei, (long long)E + i);
        int s = edge_val(ei, i);
        int pos = atomicAdd(&g_cursor[d], 1);
        g_adj[pos] = s;
    } else if (i < E + N) {  // self loops
        int n = i - E;
        int pos = atomicAdd(&g_cursor[n], 1);
        g_adj[pos] = n;
    }
}

// ------ dense GEMM Y[N,FOUT] = X[N,FIN] @ W[FIN,FOUT], fused attention logits ------
// C = FOUT/8 channels per head. Epilogue: segmented shfl reduction over C-lane
// groups produces als/ald per (node, head).
template <int FIN, int FOUT, int NPB, int LAYER>
__global__ __launch_bounds__(FOUT * NPB) void k_gemm(const float* __restrict__ Xext,
                                                     const float* __restrict__ W,
                                                     const float* __restrict__ a_src,
                                                     const float* __restrict__ a_dst, int N) {
    constexpr int C = FOUT / 8;
    const float* __restrict__ X = (LAYER == 1) ? Xext : g_h1post;
    float* __restrict__ Y = (LAYER == 1) ? g_h1pre : g_h2pre;
    float* __restrict__ als = (LAYER == 1) ? g_al1s : g_al2s;
    float* __restrict__ ald = (LAYER == 1) ? g_al1d : g_al2d;
    __shared__ float Ws[FIN * FOUT];
    __shared__ float Xs[NPB][FIN];
    int tid = threadIdx.x;
    int tx = tid % FOUT, ty = tid / FOUT;
    for (int idx = tid; idx < FIN * FOUT; idx += FOUT * NPB) Ws[idx] = W[idx];
    int n = blockIdx.x * NPB + ty;
    for (int k = tx; k < FIN; k += FOUT) Xs[ty][k] = (n < N) ? X[n * FIN + k] : 0.f;
    __syncthreads();
    float sum = 0.f;
#pragma unroll
    for (int k = 0; k < FIN; k++) sum = fmaf(Xs[ty][k], Ws[k * FOUT + tx], sum);
    if (n < N) Y[n * FOUT + tx] = sum;

    // attention logits: reduce h*a over each C-lane (contiguous) channel group
    float ps = sum * __ldg(&a_src[tx]);
    float pd = sum * __ldg(&a_dst[tx]);
#pragma unroll
    for (int off = C / 2; off > 0; off >>= 1) {
        ps += __shfl_xor_sync(0xffffffffu, ps, off);
        pd += __shfl_xor_sync(0xffffffffu, pd, off);
    }
    if (n < N && (tx % C) == 0) {
        int head = tx / C;
        als[n * 8 + head] = ps;
        ald[n * 8 + head] = pd;
    }
}

// ------ GAT aggregation: single-pass (no max shift), float4 feature lanes ------
// out[n] = (Σ_j exp(lrelu(als[src_j]+ald[n])) * h[src_j]) / (Σ_j exp(...)) + bias, then ELU.
template <int C, int LAYER>
__global__ __launch_bounds__(256) void k_agg(const float* __restrict__ bias, int N) {
    constexpr int F = 8 * C;     // 64 / 32
    constexpr int G = F / 4;     // lanes per node: 16 / 8
    constexpr int NPW = 32 / G;  // nodes per warp: 2 / 4
    const float* __restrict__ H = (LAYER == 1) ? g_h1pre : g_h2pre;
    const float* __restrict__ als = (LAYER == 1) ? g_al1s : g_al2s;
    const float* __restrict__ ald = (LAYER == 1) ? g_al1d : g_al2d;
    float* __restrict__ outp = (LAYER == 1) ? g_h1post : g_h2post;

    int warp = (blockIdx.x * blockDim.x + threadIdx.x) >> 5;
    int lane = threadIdx.x & 31;
    int sub = lane / G, gl = lane % G;
    int node = warp * NPW + sub;
    bool valid = node < N;
    int base = 0, deg = 0;
    if (valid) { base = g_rowptr[node]; deg = g_rowptr[node + 1] - base; }

    int hh = (4 * gl) / C;  // head owning this lane's 4 channels
    float adh = valid ? ald[node * 8 + hh] : 0.f;

    float ax = 0.f, ay = 0.f, az = 0.f, aw = 0.f, denom = 0.f;
#pragma unroll 2
    for (int j = 0; j < deg; j++) {
        int sid = __ldg(&g_adj[base + j]);
        float a = __ldg(&als[sid * 8 + hh]) + adh;
        a = a > 0.f ? a : 0.2f * a;
        float w = __expf(a);
        denom += w;
        float4 f = *reinterpret_cast<const float4*>(&H[sid * F + 4 * gl]);
        ax = fmaf(f.x, w, ax);
        ay = fmaf(f.y, w, ay);
        az = fmaf(f.z, w, az);
        aw = fmaf(f.w, w, aw);
    }
    if (valid) {
        float inv = 1.f / (denom + 1e-16f);
        float4 b4 = *reinterpret_cast<const float4*>(&bias[4 * gl]);
        float o0 = fmaf(ax, inv, b4.x);
        float o1 = fmaf(ay, inv, b4.y);
        float o2 = fmaf(az, inv, b4.z);
        float o3 = fmaf(aw, inv, b4.w);
        o0 = o0 > 0.f ? o0 : (expf(o0) - 1.f);  // elu
        o1 = o1 > 0.f ? o1 : (expf(o1) - 1.f);
        o2 = o2 > 0.f ? o2 : (expf(o2) - 1.f);
        o3 = o3 > 0.f ? o3 : (expf(o3) - 1.f);
        *reinterpret_cast<float4*>(&outp[node * F + 4 * gl]) = make_float4(o0, o1, o2, o3);
    }
}

// ---------------- fold MHA(v-path)+out_proj+fc into one 16x32 matrix ----------------
__global__ void k_prep(const float* __restrict__ in_w, const float* __restrict__ in_b,
                       const float* __restrict__ ow, const float* __restrict__ ob,
                       const float* __restrict__ fw, const float* __restrict__ fb) {
    __shared__ float T[32 * 32];
    __shared__ float u[32];
    int tid = threadIdx.x;  // 1024
    {
        int r = tid >> 5, j = tid & 31;
        float acc = 0.f;
        for (int p = 0; p < 32; p++) acc = fmaf(ow[r * 32 + p], in_w[(64 + p) * 32 + j], acc);
        T[r * 32 + j] = acc;
    }
    if (tid < 32) {
        float acc = ob[tid];
        for (int p = 0; p < 32; p++) acc = fmaf(ow[tid * 32 + p], in_b[64 + p], acc);
        u[tid] = acc;
    }
    __syncthreads();
    if (tid < 512) {
        int i = tid >> 5, j = tid & 31;
        float acc = 0.f;
        for (int r = 0; r < 32; r++) acc = fmaf(fw[i * 32 + r], T[r * 32 + j], acc);
        g_Mf[i * 32 + j] = acc;
    }
    if (tid < 16) {
        float acc = fb[tid];
        for (int r = 0; r < 32; r++) acc = fmaf(fw[tid * 32 + r], u[r], acc);
        g_cf[tid] = acc;
    }
}

// ---------------- logits + log_softmax ----------------
__global__ void k_logits(float* __restrict__ out, int N) {
    int n = blockIdx.x * blockDim.x + threadIdx.x;
    if (n >= N) return;
    float hr[32];
#pragma unroll
    for (int q = 0; q < 8; q++) {
        float4 v = *reinterpret_cast<const float4*>(&g_h2post[n * 32 + q * 4]);
        hr[q * 4 + 0] = v.x; hr[q * 4 + 1] = v.y; hr[q * 4 + 2] = v.z; hr[q * 4 + 3] = v.w;
    }
    float l[16];
#pragma unroll
    for (int i = 0; i < 16; i++) {
        float acc = g_cf[i];
#pragma unroll
        for (int j = 0; j < 32; j++) acc = fmaf(g_Mf[i * 32 + j], hr[j], acc);
        l[i] = acc;
    }
    float mx = l[0];
#pragma unroll
    for (int i = 1; i < 16; i++) mx = fmaxf(mx, l[i]);
    float se = 0.f;
#pragma unroll
    for (int i = 0; i < 16; i++) se += expf(l[i] - mx);
    float lse = mx + logf(se);
#pragma unroll
    for (int q = 0; q < 4; q++) {
        float4 v = make_float4(l[q * 4 + 0] - lse, l[q * 4 + 1] - lse,
                               l[q * 4 + 2] - lse, l[q * 4 + 3] - lse);
        *reinterpret_cast<float4*>(&out[n * 16 + q * 4]) = v;
    }
}

// ---------------- launcher ----------------
extern "C" void kernel_launch(void* const* d_in, const int* in_sizes, int n_in,
                              void* d_out, int out_size) {
    const float* x = (const float*)d_in[0];
    const void* ei = d_in[1];
    const float* W1 = (const float*)d_in[2];
    const float* a1s = (const float*)d_in[3];
    const float* a1d = (const float*)d_in[4];
    const float* b1 = (const float*)d_in[5];
    const float* W2 = (const float*)d_in[6];
    const float* a2s = (const float*)d_in[7];
    const float* a2d = (const float*)d_in[8];
    const float* b2 = (const float*)d_in[9];
    const float* ipw = (const float*)d_in[10];
    const float* ipb = (const float*)d_in[11];
    const float* opw = (const float*)d_in[12];
    const float* opb = (const float*)d_in[13];
    const float* fw = (const float*)d_in[14];
    const float* fb = (const float*)d_in[15];

    int N = in_sizes[0] / 128;
    int E = in_sizes[1] / 2;

    // CSR by dst (reused by both GAT layers)
    k_zero<<<(N + 255) / 256, 256>>>((const unsigned long long*)ei, N, E);
    k_count<<<(E + 255) / 256, 256>>>(ei, E);
    int nb = (N + 1023) / 1024;
    k_blocksum<<<nb, 1024>>>(N);
    k_scanpart<<<1, 32>>>(nb);
    k_scan<<<nb, 1024>>>(N);
    k_scatter<<<(E + N + 255) / 256, 256>>>(ei, E, N);

    // GAT layer 1: 128 -> 8 heads x 8 (GEMM + fused logits, then 1-pass agg)
    k_gemm<128, 64, 4, 1><<<(N + 3) / 4, 256>>>(x, W1, a1s, a1d, N);
    k_agg<8, 1><<<(N + 15) / 16, 256>>>(b1, N);

    // GAT layer 2: 64 -> 8 heads x 4
    k_gemm<64, 32, 8, 2><<<(N + 7) / 8, 256>>>(x, W2, a2s, a2d, N);
    k_agg<4, 2><<<(N + 31) / 32, 256>>>(b2, N);

    // collapsed MHA + fc + log_softmax
    k_prep<<<1, 1024>>>(ipw, ipb, opw, opb, fw, fb);
    k_logits<<<(N + 127) / 128, 128>>>((float*)d_out, N);
}